// round 14
// baseline (speedup 1.0000x reference)
#include <cuda_runtime.h>
#include <cuda_fp16.h>

#define IMH 4096
#define IMW 4096
#define RAD 8
#define BX 128
#define LCOLS 256                 // loaded columns (2 per thread)
#define OUT_W 240
#define CHUNK 8
#define SEGH 128
#define NSTRIPS ((IMW + OUT_W - 1) / OUT_W)   // 18
#define NSEG (IMH / SEGH)                     // 32 -> grid 18*32*3 = 1728 (2.34 waves @ 5 CTAs)
#define EPSF 1e-4f

// 44.1 KB -> 5 CTAs/SM. vb stride 258 float2 (2064 B: 16B-aligned rows for
// STS.128). HF LDS.64 phases have constant hr (hr = tid>>4) -> each 16-lane
// phase spans hs=0..15 with 8B-offsets 15*hs (distinct mod 16) -> conflict-free.
struct SmemT {
    float2 vb_ip [CHUNK][LCOLS + 2];   // (vsum_i, vsum_p) per column
    float2 vb_pii[CHUNK][LCOLS + 2];   // (vsum_pi, vsum_ii)
    float  icen  [CHUNK][LCOLS + 2];   // center-row i
    __half qbuf  [CHUNK][OUT_W + 2];   // staged outputs
};

__global__ void __launch_bounds__(BX, 5)
gf_kernel(const float* __restrict__ gI, const float* __restrict__ gP,
          float* __restrict__ gQ)
{
    extern __shared__ unsigned char smem_raw[];
    SmemT& sm = *reinterpret_cast<SmemT*>(smem_raw);

    const int tid = threadIdx.x;
    const int ys  = blockIdx.y * SEGH;
    const int chOff = blockIdx.z * IMH * IMW;
    const float* Ic = gI + chOff;
    const float* Pc = gP + chOff;
    float*       Qc = gQ + chOff;

    const int X0 = blockIdx.x * OUT_W;
    const int c0 = X0 - RAD + 2 * tid;            // even; thread owns c0, c0+1
    const bool cvalid = (c0 >= 0) && (c0 < IMW);  // pair never straddles border

    float2 vsi  = make_float2(0.f, 0.f), vsp  = make_float2(0.f, 0.f);
    float2 vspi = make_float2(0.f, 0.f), vsii = make_float2(0.f, 0.f);
    float2 dly[8];                                // i delay line (col pair)
    #pragma unroll
    for (int k = 0; k < 8; ++k) dly[k] = make_float2(0.f, 0.f);

    // Warmup: rows ys-9 .. ys+7 (17 rows); last 8 pushes fill the delay line.
    #pragma unroll
    for (int w = 0; w < 17; ++w) {
        const int yl = ys - RAD - 1 + w;
        float2 iv = make_float2(0.f, 0.f), pv = make_float2(0.f, 0.f);
        if (yl >= 0 && cvalid) {
            iv = *reinterpret_cast<const float2*>(Ic + yl * IMW + c0);
            pv = *reinterpret_cast<const float2*>(Pc + yl * IMW + c0);
        }
        vsi.x  += iv.x;        vsi.y  += iv.y;
        vsp.x  += pv.x;        vsp.y  += pv.y;
        vspi.x += iv.x * pv.x; vspi.y += iv.y * pv.y;
        vsii.x += iv.x * iv.x; vsii.y += iv.y * iv.y;
        #pragma unroll
        for (int k = 0; k < 7; ++k) dly[k] = dly[k + 1];
        dly[7] = iv;
    }

    const int hr = tid >> 4;        // HF row within chunk (0..7)
    const int hs = tid & 15;        // HF x-split (16 splits x 15 cols)
    const int xbase = RAD + 15 * hs;

    for (int ck = 0; ck < SEGH / CHUNK; ++ck) {
        const int y0 = ys + ck * CHUNK;

        // ---- V phase: vertical sliding box sums, 2 cols/thread (LDG.64);
        // trailing edge re-read from gmem (L2-resident). ----
        #pragma unroll
        for (int r = 0; r < CHUNK; ++r) {
            const int yl = y0 + r + RAD;
            const int yt = y0 + r - RAD - 1;
            float2 iv = make_float2(0.f, 0.f), pv = make_float2(0.f, 0.f);
            float2 it = make_float2(0.f, 0.f), pt = make_float2(0.f, 0.f);
            if (yl < IMH && cvalid) {
                iv = *reinterpret_cast<const float2*>(Ic + yl * IMW + c0);
                pv = *reinterpret_cast<const float2*>(Pc + yl * IMW + c0);
            }
            if (yt >= 0 && cvalid) {
                it = *reinterpret_cast<const float2*>(Ic + yt * IMW + c0);
                pt = *reinterpret_cast<const float2*>(Pc + yt * IMW + c0);
            }
            *reinterpret_cast<float2*>(&sm.icen[r][2 * tid]) = dly[0];
            #pragma unroll
            for (int k = 0; k < 7; ++k) dly[k] = dly[k + 1];
            dly[7] = iv;

            vsi.x  += iv.x - it.x;                 vsi.y  += iv.y - it.y;
            vsp.x  += pv.x - pt.x;                 vsp.y  += pv.y - pt.y;
            vspi.x += iv.x * pv.x - it.x * pt.x;   vspi.y += iv.y * pv.y - it.y * pt.y;
            vsii.x += iv.x * iv.x - it.x * it.x;   vsii.y += iv.y * iv.y - it.y * it.y;

            *reinterpret_cast<float4*>(&sm.vb_ip [r][2 * tid]) =
                make_float4(vsi.x, vsp.x, vsi.y, vsp.y);
            *reinterpret_cast<float4*>(&sm.vb_pii[r][2 * tid]) =
                make_float4(vspi.x, vsii.x, vspi.y, vsii.y);
        }
        __syncthreads();   // B1: vbuf + icen ready

        // ---- HF phase: horizontal sliding sums + guided-filter math ----
        {
            const int y = y0 + hr;
            const int ny = min(y + RAD, IMH - 1) - max(y - RAD, 0) + 1;

            float hi = 0.f, hp = 0.f, hpi = 0.f, hii = 0.f;
            #pragma unroll
            for (int d = -RAD; d <= RAD; ++d) {
                const float2 a2 = sm.vb_ip [hr][xbase + d];
                const float2 b2 = sm.vb_pii[hr][xbase + d];
                hi += a2.x; hp += a2.y; hpi += b2.x; hii += b2.y;
            }
            #pragma unroll
            for (int j = 0; j < 15; ++j) {
                const int x = xbase + j;
                if (j > 0) {
                    const float2 aL = sm.vb_ip [hr][x + RAD];
                    const float2 aT = sm.vb_ip [hr][x - RAD - 1];
                    const float2 bL = sm.vb_pii[hr][x + RAD];
                    const float2 bT = sm.vb_pii[hr][x - RAD - 1];
                    hi  += aL.x - aT.x; hp  += aL.y - aT.y;
                    hpi += bL.x - bT.x; hii += bL.y - bT.y;
                }
                const int gx = X0 + x - RAD;
                const int nx = min(gx + RAD, IMW - 1) - max(gx - RAD, 0) + 1;
                const float invN = __fdividef(1.0f, (float)(ny * nx));

                const float m_i  = hi  * invN;
                const float m_p  = hp  * invN;
                const float m_pi = hpi * invN;
                const float m_ii = hii * invN;
                const float cov_ip = m_pi - m_p * m_i;
                const float cov_ii = m_ii - m_i * m_i;
                const float a = __fdividef(cov_ip, cov_ii + EPSF);
                const float b = m_p - a * m_i;
                const float icen = sm.icen[hr][x];
                const float q = fminf(fmaxf(a * icen + b, 0.0f), 1.0f);
                sm.qbuf[hr][x - RAD] = __float2half_rn(q);
            }
        }
        __syncthreads();   // B2: qbuf ready, vbuf free

        // ---- Q phase: coalesced float2 store (2 cols/thread); overlaps
        // next chunk's V phase ----
        if (tid < OUT_W / 2) {
            const int gx0 = X0 + 2 * tid;
            if (gx0 < IMW) {    // pair never straddles (gx0 even)
                #pragma unroll
                for (int rr = 0; rr < CHUNK; ++rr) {
                    const __half2 h2 =
                        *reinterpret_cast<const __half2*>(&sm.qbuf[rr][2 * tid]);
                    const float2 f2 = __half22float2(h2);
                    *reinterpret_cast<float2*>(Qc + (y0 + rr) * IMW + gx0) = f2;
                }
            }
        }
    }
}

extern "C" void kernel_launch(void* const* d_in, const int* in_sizes, int n_in,
                              void* d_out, int out_size)
{
    const float* I = (const float*)d_in[0];
    const float* P = (const float*)d_in[1];
    float*       Q = (float*)d_out;

    cudaFuncSetAttribute(gf_kernel, cudaFuncAttributeMaxDynamicSharedMemorySize,
                         (int)sizeof(SmemT));

    dim3 grid(NSTRIPS, NSEG, 3);
    gf_kernel<<<grid, BX, sizeof(SmemT)>>>(I, P, Q);
}

// round 15
// speedup vs baseline: 1.1686x; 1.1686x over previous
#include <cuda_runtime.h>
#include <cuda_fp16.h>

#define IMH 4096
#define IMW 4096
#define RAD 8
#define BX 128
#define OUT_W 112
#define CHUNK 16
#define SEGH 256
#define NSTRIPS ((IMW + OUT_W - 1) / OUT_W)   // 37
#define NSEG (IMH / SEGH)                     // 16 -> grid 1776
#define EPSF 1e-4f

// 44.9 KB -> 5 CTAs/SM. Odd strides keep row-indexed access conflict-free.
struct SmemT {
    float2 vb_ip [CHUNK][BX + 1];   // (vsum_i, vsum_p)
    float2 vb_pii[CHUNK][BX + 1];   // (vsum_pi, vsum_ii)
    float  icen  [CHUNK][BX + 1];   // center-row i (from reg delay line)
    __half qbuf  [CHUNK][OUT_W + 1];// staged outputs
};

__global__ void __launch_bounds__(BX, 5)
gf_kernel(const float* __restrict__ gI, const float* __restrict__ gP,
          float* __restrict__ gQ)
{
    extern __shared__ unsigned char smem_raw[];
    SmemT& sm = *reinterpret_cast<SmemT*>(smem_raw);

    const int tid = threadIdx.x;
    const int ys  = blockIdx.y * SEGH;
    const int chOff = blockIdx.z * IMH * IMW;
    const float* Ic = gI + chOff;
    const float* Pc = gP + chOff;
    float*       Qc = gQ + chOff;

    const int X0 = blockIdx.x * OUT_W;
    const int c  = X0 - RAD + tid;
    const bool cvalid = (c >= 0) && (c < IMW);

    float vs_i = 0.f, vs_p = 0.f, vs_pi = 0.f, vs_ii = 0.f;
    float dly[8];
    #pragma unroll
    for (int k = 0; k < 8; ++k) dly[k] = 0.f;

    // Warmup: rows ys-9 .. ys+7 (17 rows); last 8 pushes fill the delay line.
    #pragma unroll
    for (int w = 0; w < 17; ++w) {
        const int yl = ys - RAD - 1 + w;
        float iv = 0.f, pv = 0.f;
        if (yl >= 0 && cvalid) {
            iv = Ic[yl * IMW + c];
            pv = Pc[yl * IMW + c];
        }
        vs_i += iv; vs_p += pv; vs_pi += iv * pv; vs_ii += iv * iv;
        #pragma unroll
        for (int k = 0; k < 7; ++k) dly[k] = dly[k + 1];
        dly[7] = iv;
    }

    const int hr = tid & 15;        // HF row within chunk
    const int hs = tid >> 4;        // HF x-split (8 splits x 14 cols)
    const int xbase = RAD + 14 * hs;

    for (int ck = 0; ck < SEGH / CHUNK; ++ck) {
        const int y0 = ys + ck * CHUNK;

        // ---- V phase (unchanged from R12) ----
        #pragma unroll 8
        for (int r = 0; r < CHUNK; ++r) {
            const int yl = y0 + r + RAD;
            const int yt = y0 + r - RAD - 1;
            float iv = 0.f, pv = 0.f, it = 0.f, pt = 0.f;
            if (yl < IMH && cvalid) {
                iv = __ldg(Ic + yl * IMW + c);
                pv = __ldg(Pc + yl * IMW + c);
            }
            if (yt >= 0 && cvalid) {
                it = __ldg(Ic + yt * IMW + c);
                pt = __ldg(Pc + yt * IMW + c);
            }
            sm.icen[r][tid] = dly[0];
            #pragma unroll
            for (int k = 0; k < 7; ++k) dly[k] = dly[k + 1];
            dly[7] = iv;
            vs_i  += iv - it;
            vs_p  += pv - pt;
            vs_pi += iv * pv - it * pt;
            vs_ii += iv * iv - it * it;
            sm.vb_ip [r][tid] = make_float2(vs_i, vs_p);
            sm.vb_pii[r][tid] = make_float2(vs_pi, vs_ii);
        }
        __syncthreads();   // B1: vbuf + icen ready

        // ---- HF phase: TWO independent sliding chains per thread.
        // Chain A -> cols xbase..xbase+6, chain B -> xbase+7..xbase+13.
        // Independent accumulators double per-thread ILP, hiding LDS latency. ----
        {
            const int y = y0 + hr;
            const int ny = min(y + RAD, IMH - 1) - max(y - RAD, 0) + 1;
            const int xb2 = xbase + 7;

            float hiA = 0.f, hpA = 0.f, hpiA = 0.f, hiiA = 0.f;
            float hiB = 0.f, hpB = 0.f, hpiB = 0.f, hiiB = 0.f;
            // Fused init over the union window [xbase-8, xbase+15]:
            // d in [-8,8] feeds A; d in [-1,15] feeds B (shared loads).
            #pragma unroll
            for (int d = -RAD; d <= RAD + 7; ++d) {
                const float2 a2 = sm.vb_ip [hr][xbase + d];
                const float2 b2 = sm.vb_pii[hr][xbase + d];
                if (d <= RAD)      { hiA += a2.x; hpA += a2.y; hpiA += b2.x; hiiA += b2.y; }
                if (d >= 7 - RAD)  { hiB += a2.x; hpB += a2.y; hpiB += b2.x; hiiB += b2.y; }
            }
            #pragma unroll
            for (int j = 0; j < 7; ++j) {
                const int xA = xbase + j;
                const int xB = xb2 + j;
                if (j > 0) {
                    const float2 aLA = sm.vb_ip [hr][xA + RAD];
                    const float2 aTA = sm.vb_ip [hr][xA - RAD - 1];
                    const float2 bLA = sm.vb_pii[hr][xA + RAD];
                    const float2 bTA = sm.vb_pii[hr][xA - RAD - 1];
                    const float2 aLB = sm.vb_ip [hr][xB + RAD];
                    const float2 aTB = sm.vb_ip [hr][xB - RAD - 1];
                    const float2 bLB = sm.vb_pii[hr][xB + RAD];
                    const float2 bTB = sm.vb_pii[hr][xB - RAD - 1];
                    hiA  += aLA.x - aTA.x; hpA  += aLA.y - aTA.y;
                    hpiA += bLA.x - bTA.x; hiiA += bLA.y - bTA.y;
                    hiB  += aLB.x - aTB.x; hpB  += aLB.y - aTB.y;
                    hpiB += bLB.x - bTB.x; hiiB += bLB.y - bTB.y;
                }
                // Chain A output
                {
                    const int gx = X0 + xA - RAD;
                    const int nx = min(gx + RAD, IMW - 1) - max(gx - RAD, 0) + 1;
                    const float invN = __fdividef(1.0f, (float)(ny * nx));
                    const float m_i  = hiA  * invN;
                    const float m_p  = hpA  * invN;
                    const float m_pi = hpiA * invN;
                    const float m_ii = hiiA * invN;
                    const float cov_ip = m_pi - m_p * m_i;
                    const float cov_ii = m_ii - m_i * m_i;
                    const float a = __fdividef(cov_ip, cov_ii + EPSF);
                    const float b = m_p - a * m_i;
                    const float icen = sm.icen[hr][xA];
                    const float q = fminf(fmaxf(a * icen + b, 0.0f), 1.0f);
                    sm.qbuf[hr][xA - RAD] = __float2half_rn(q);
                }
                // Chain B output
                {
                    const int gx = X0 + xB - RAD;
                    const int nx = min(gx + RAD, IMW - 1) - max(gx - RAD, 0) + 1;
                    const float invN = __fdividef(1.0f, (float)(ny * nx));
                    const float m_i  = hiB  * invN;
                    const float m_p  = hpB  * invN;
                    const float m_pi = hpiB * invN;
                    const float m_ii = hiiB * invN;
                    const float cov_ip = m_pi - m_p * m_i;
                    const float cov_ii = m_ii - m_i * m_i;
                    const float a = __fdividef(cov_ip, cov_ii + EPSF);
                    const float b = m_p - a * m_i;
                    const float icen = sm.icen[hr][xB];
                    const float q = fminf(fmaxf(a * icen + b, 0.0f), 1.0f);
                    sm.qbuf[hr][xB - RAD] = __float2half_rn(q);
                }
            }
        }
        __syncthreads();   // B2: qbuf ready, vbuf free

        // ---- Q phase: coalesced store; overlaps next chunk's V phase ----
        if (tid < OUT_W && (X0 + tid) < IMW) {
            #pragma unroll 4
            for (int rr = 0; rr < CHUNK; ++rr) {
                Qc[(y0 + rr) * IMW + X0 + tid] = __half2float(sm.qbuf[rr][tid]);
            }
        }
    }
}

extern "C" void kernel_launch(void* const* d_in, const int* in_sizes, int n_in,
                              void* d_out, int out_size)
{
    const float* I = (const float*)d_in[0];
    const float* P = (const float*)d_in[1];
    float*       Q = (float*)d_out;

    cudaFuncSetAttribute(gf_kernel, cudaFuncAttributeMaxDynamicSharedMemorySize,
                         (int)sizeof(SmemT));

    dim3 grid(NSTRIPS, NSEG, 3);
    gf_kernel<<<grid, BX, sizeof(SmemT)>>>(I, P, Q);
}

// round 17
// speedup vs baseline: 1.1800x; 1.0098x over previous
#include <cuda_runtime.h>
#include <cuda_fp16.h>

#define IMH 4096
#define IMW 4096
#define RAD 8
#define BX 128
#define OUT_W 112
#define CHUNK 16
#define SEGH 128
#define NSTRIPS ((IMW + OUT_W - 1) / OUT_W)   // 37
#define NSEG (IMH / SEGH)                     // 32 -> grid 3552 = 4.8 waves @ 5 CTAs/SM (tail = 592 = 4x148, uniform)
#define EPSF 1e-4f

// 44.9 KB -> 5 CTAs/SM. Odd strides keep row-indexed access conflict-free.
struct SmemT {
    float2 vb_ip [CHUNK][BX + 1];   // (vsum_i, vsum_p)
    float2 vb_pii[CHUNK][BX + 1];   // (vsum_pi, vsum_ii)
    float  icen  [CHUNK][BX + 1];   // center-row i (from reg delay line)
    __half qbuf  [CHUNK][OUT_W + 1];// staged outputs
};

__global__ void __launch_bounds__(BX, 5)
gf_kernel(const float* __restrict__ gI, const float* __restrict__ gP,
          float* __restrict__ gQ)
{
    extern __shared__ unsigned char smem_raw[];
    SmemT& sm = *reinterpret_cast<SmemT*>(smem_raw);

    const int tid = threadIdx.x;
    const int ys  = blockIdx.y * SEGH;
    const int chOff = blockIdx.z * IMH * IMW;
    const float* Ic = gI + chOff;
    const float* Pc = gP + chOff;
    float*       Qc = gQ + chOff;

    const int X0 = blockIdx.x * OUT_W;
    const int c  = X0 - RAD + tid;
    const bool cvalid = (c >= 0) && (c < IMW);

    float vs_i = 0.f, vs_p = 0.f, vs_pi = 0.f, vs_ii = 0.f;
    float dly[8];
    #pragma unroll
    for (int k = 0; k < 8; ++k) dly[k] = 0.f;

    // Warmup: rows ys-9 .. ys+7 (17 rows); last 8 pushes fill the delay line.
    #pragma unroll
    for (int w = 0; w < 17; ++w) {
        const int yl = ys - RAD - 1 + w;
        float iv = 0.f, pv = 0.f;
        if (yl >= 0 && cvalid) {
            iv = Ic[yl * IMW + c];
            pv = Pc[yl * IMW + c];
        }
        vs_i += iv; vs_p += pv; vs_pi += iv * pv; vs_ii += iv * iv;
        #pragma unroll
        for (int k = 0; k < 7; ++k) dly[k] = dly[k + 1];
        dly[7] = iv;
    }

    const int hr = tid & 15;        // HF row within chunk
    const int hs = tid >> 4;        // HF x-split (8 splits x 14 cols)
    const int xbase = RAD + 14 * hs;

    for (int ck = 0; ck < SEGH / CHUNK; ++ck) {
        const int y0 = ys + ck * CHUNK;

        // ---- V phase: vertical sliding box sums; trailing edge re-read
        // from gmem (L2-resident). Unroll 8 front-batches LDGs (MLP). ----
        #pragma unroll 8
        for (int r = 0; r < CHUNK; ++r) {
            const int yl = y0 + r + RAD;
            const int yt = y0 + r - RAD - 1;
            float iv = 0.f, pv = 0.f, it = 0.f, pt = 0.f;
            if (yl < IMH && cvalid) {
                iv = __ldg(Ic + yl * IMW + c);
                pv = __ldg(Pc + yl * IMW + c);
            }
            if (yt >= 0 && cvalid) {
                it = __ldg(Ic + yt * IMW + c);
                pt = __ldg(Pc + yt * IMW + c);
            }
            sm.icen[r][tid] = dly[0];
            #pragma unroll
            for (int k = 0; k < 7; ++k) dly[k] = dly[k + 1];
            dly[7] = iv;
            vs_i  += iv - it;
            vs_p  += pv - pt;
            vs_pi += iv * pv - it * pt;
            vs_ii += iv * iv - it * it;
            sm.vb_ip [r][tid] = make_float2(vs_i, vs_p);
            sm.vb_pii[r][tid] = make_float2(vs_pi, vs_ii);
        }
        __syncthreads();   // B1: vbuf + icen ready

        // ---- HF phase: two independent sliding chains per thread ----
        {
            const int y = y0 + hr;
            const int ny = min(y + RAD, IMH - 1) - max(y - RAD, 0) + 1;
            const int xb2 = xbase + 7;

            float hiA = 0.f, hpA = 0.f, hpiA = 0.f, hiiA = 0.f;
            float hiB = 0.f, hpB = 0.f, hpiB = 0.f, hiiB = 0.f;
            #pragma unroll
            for (int d = -RAD; d <= RAD + 7; ++d) {
                const float2 a2 = sm.vb_ip [hr][xbase + d];
                const float2 b2 = sm.vb_pii[hr][xbase + d];
                if (d <= RAD)      { hiA += a2.x; hpA += a2.y; hpiA += b2.x; hiiA += b2.y; }
                if (d >= 7 - RAD)  { hiB += a2.x; hpB += a2.y; hpiB += b2.x; hiiB += b2.y; }
            }
            #pragma unroll
            for (int j = 0; j < 7; ++j) {
                const int xA = xbase + j;
                const int xB = xb2 + j;
                if (j > 0) {
                    const float2 aLA = sm.vb_ip [hr][xA + RAD];
                    const float2 aTA = sm.vb_ip [hr][xA - RAD - 1];
                    const float2 bLA = sm.vb_pii[hr][xA + RAD];
                    const float2 bTA = sm.vb_pii[hr][xA - RAD - 1];
                    const float2 aLB = sm.vb_ip [hr][xB + RAD];
                    const float2 aTB = sm.vb_ip [hr][xB - RAD - 1];
                    const float2 bLB = sm.vb_pii[hr][xB + RAD];
                    const float2 bTB = sm.vb_pii[hr][xB - RAD - 1];
                    hiA  += aLA.x - aTA.x; hpA  += aLA.y - aTA.y;
                    hpiA += bLA.x - bTA.x; hiiA += bLA.y - bTA.y;
                    hiB  += aLB.x - aTB.x; hpB  += aLB.y - aTB.y;
                    hpiB += bLB.x - bTB.x; hiiB += bLB.y - bTB.y;
                }
                {
                    const int gx = X0 + xA - RAD;
                    const int nx = min(gx + RAD, IMW - 1) - max(gx - RAD, 0) + 1;
                    const float invN = __fdividef(1.0f, (float)(ny * nx));
                    const float m_i  = hiA  * invN;
                    const float m_p  = hpA  * invN;
                    const float m_pi = hpiA * invN;
                    const float m_ii = hiiA * invN;
                    const float cov_ip = m_pi - m_p * m_i;
                    const float cov_ii = m_ii - m_i * m_i;
                    const float a = __fdividef(cov_ip, cov_ii + EPSF);
                    const float b = m_p - a * m_i;
                    const float icen = sm.icen[hr][xA];
                    const float q = fminf(fmaxf(a * icen + b, 0.0f), 1.0f);
                    sm.qbuf[hr][xA - RAD] = __float2half_rn(q);
                }
                {
                    const int gx = X0 + xB - RAD;
                    const int nx = min(gx + RAD, IMW - 1) - max(gx - RAD, 0) + 1;
                    const float invN = __fdividef(1.0f, (float)(ny * nx));
                    const float m_i  = hiB  * invN;
                    const float m_p  = hpB  * invN;
                    const float m_pi = hpiB * invN;
                    const float m_ii = hiiB * invN;
                    const float cov_ip = m_pi - m_p * m_i;
                    const float cov_ii = m_ii - m_i * m_i;
                    const float a = __fdividef(cov_ip, cov_ii + EPSF);
                    const float b = m_p - a * m_i;
                    const float icen = sm.icen[hr][xB];
                    const float q = fminf(fmaxf(a * icen + b, 0.0f), 1.0f);
                    sm.qbuf[hr][xB - RAD] = __float2half_rn(q);
                }
            }
        }
        __syncthreads();   // B2: qbuf ready, vbuf free

        // ---- Q phase: coalesced store; overlaps next chunk's V phase ----
        if (tid < OUT_W && (X0 + tid) < IMW) {
            #pragma unroll 4
            for (int rr = 0; rr < CHUNK; ++rr) {
                Qc[(y0 + rr) * IMW + X0 + tid] = __half2float(sm.qbuf[rr][tid]);
            }
        }
    }
}

extern "C" void kernel_launch(void* const* d_in, const int* in_sizes, int n_in,
                              void* d_out, int out_size)
{
    const float* I = (const float*)d_in[0];
    const float* P = (const float*)d_in[1];
    float*       Q = (float*)d_out;

    cudaFuncSetAttribute(gf_kernel, cudaFuncAttributeMaxDynamicSharedMemorySize,
                         (int)sizeof(SmemT));

    dim3 grid(NSTRIPS, NSEG, 3);
    gf_kernel<<<grid, BX, sizeof(SmemT)>>>(I, P, Q);
}